// round 8
// baseline (speedup 1.0000x reference)
#include <cuda_runtime.h>
#include <cstdint>

// ============================================================================
// SpectralNetLoss:
//   2n·loss = Σ_ij W_ij(sq_i + sq_j) − 2 Σ_ij W_ij (y_i·y_j)
// ALL terms via one tf32 mma.sync GEMM  U = W × B̃, B̃ = [Y | sq | 1 | 0…] (72 cols):
//   U[:,0..63] folded with Y  -> dot term
//   U[:,64] = (W·sq)_i, U[:,65] = rowsum r_i -> term1 = Σ U[i,64] + sq_i·U[i,65]
// A-only 3-stage cp.async SMEM pipeline; B̃ pre-packed in fragment order (L1-hot);
// 256 thr, 2Mx2N warp tiling, 3 CTAs/SM; KSPLIT=7 -> grid 448 (one wave).
// ============================================================================

#define N_DIM     8192
#define KF        64
#define M_TILE    128
#define KCHUNK    32
#define KSPLIT    7
#define RS        36                        // padded A row stride (floats)
#define NFRAG     9                         // 9 n8 fragments = 72 B̃ columns

#define A_FLOATS  (M_TILE * RS)             // 4608
#define STAGE_FLOATS A_FLOATS
#define STAGE_BYTES  (STAGE_FLOATS * 4)     // 18432
#define SMEM_BYTES   (3 * STAGE_BYTES)      // 55296

#define NCK       (N_DIM / 8)               // 1024 k-octets (ck = chunk*4+kst)

// B̃ packed in mma-fragment order: float2[(ck*9 + nn)*32 + lane]
//   = ( B̃[ck*8+q][nn*8+g], B̃[ck*8+q+4][nn*8+g] ),  lane = g*4+q
__device__ float g_Bp[(size_t)NCK * NFRAG * 64];
__device__ float g_sq[N_DIM];

// ---------------------------------------------------------------- helpers
__device__ __forceinline__ uint32_t smem_u32(const void* p) {
    uint32_t a;
    asm("{ .reg .u64 t; cvta.to.shared.u64 t, %1; cvt.u32.u64 %0, t; }"
        : "=r"(a) : "l"(p));
    return a;
}
__device__ __forceinline__ void cp_async16(uint32_t dst, const void* src) {
    asm volatile("cp.async.cg.shared.global [%0], [%1], 16;"
                 :: "r"(dst), "l"(src));
}
__device__ __forceinline__ void cp_commit() {
    asm volatile("cp.async.commit_group;" ::: "memory");
}
__device__ __forceinline__ void cp_wait2() {
    asm volatile("cp.async.wait_group 2;" ::: "memory");
}
__device__ __forceinline__ void mma_tf32(float* c, const uint32_t* a,
                                         const uint32_t* b) {
    asm volatile(
        "mma.sync.aligned.m16n8k8.row.col.f32.tf32.tf32.f32 "
        "{%0,%1,%2,%3}, {%4,%5,%6,%7}, {%8,%9}, {%0,%1,%2,%3};"
        : "+f"(c[0]), "+f"(c[1]), "+f"(c[2]), "+f"(c[3])
        : "r"(a[0]), "r"(a[1]), "r"(a[2]), "r"(a[3]), "r"(b[0]), "r"(b[1]));
}

// ---------------------------------------------------------------- prep 1: sq
__global__ void spec_prep1(const float* __restrict__ Y, float* __restrict__ out) {
    int j = blockIdx.x * blockDim.x + threadIdx.x;
    if (j == 0) out[0] = 0.0f;
    if (j >= N_DIM) return;
    const float4* yp = (const float4*)(Y + (size_t)j * KF);
    float sq = 0.0f;
#pragma unroll
    for (int q = 0; q < 16; q++) {
        float4 y = yp[q];
        sq += y.x * y.x + y.y * y.y + y.z * y.z + y.w * y.w;
    }
    g_sq[j] = sq;
}

// ---------------------------------------------------------------- prep 2: pack B̃
__global__ void spec_prep2(const float* __restrict__ Y) {
    int u = blockIdx.x * blockDim.x + threadIdx.x;   // float2 index, < 294912
    int lane = u & 31;
    int q = lane & 3;
    int g = lane >> 2;
    int cn = u >> 5;                                  // ck*9 + nn
    int nn = cn % NFRAG;
    int ck = cn / NFRAG;
    int k  = ck * 8 + q;
    float v0, v1;
    if (nn < 8) {
        int col = nn * 8 + g;
        v0 = Y[(size_t)k * KF + col];
        v1 = Y[(size_t)(k + 4) * KF + col];
    } else {                                          // cols 64..71: sq | 1 | 0
        v0 = (g == 0) ? g_sq[k]     : (g == 1 ? 1.0f : 0.0f);
        v1 = (g == 0) ? g_sq[k + 4] : (g == 1 ? 1.0f : 0.0f);
    }
    ((float2*)g_Bp)[u] = make_float2(v0, v1);
}

// ---------------------------------------------------------------- A loader
__device__ __forceinline__ void load_chunk(uint32_t sdst, const float* wp,
                                           int tid) {
#pragma unroll
    for (int u = 0; u < 4; u++) {
        int idx = tid + u * 256;                      // 0..1023: 128 rows x 8 f4
        int r = idx >> 3, sg = idx & 7;
        cp_async16(sdst + (uint32_t)(r * RS + sg * 4) * 4,
                   wp + (size_t)r * N_DIM + sg * 4);
    }
}

// ---------------------------------------------------------------- main
__global__ void __launch_bounds__(256, 3)
spec_main(const float* __restrict__ W, const float* __restrict__ Y,
          float* __restrict__ out) {
    extern __shared__ float smem[];
    const uint32_t sb = smem_u32(smem);

    const int tid = threadIdx.x;
    const int w   = tid >> 5;
    const int lid = tid & 31;
    const int q   = lid & 3;
    const int g   = lid >> 2;
    const int mg  = w >> 1;            // 0..3: 32-row group
    const int ng  = w & 1;             // 0..1: 32-col group

    const int bx    = blockIdx.x;
    const int mtile = bx & 63;
    const int ks    = bx >> 6;                         // 0..6
    const int m0    = mtile * M_TILE;
    const int c0    = ks * 36 + (ks < 4 ? ks : 4);     // first chunk index
    const int nch   = 36 + (ks < 4 ? 1 : 0);           // 37 or 36 chunks

    const float* wbase = W + (size_t)m0 * N_DIM + (size_t)c0 * KCHUNK;
    const float2* Bp2  = (const float2*)g_Bp;

    float acc[2][4][4];
    float acc_e[2][4];
#pragma unroll
    for (int mt = 0; mt < 2; mt++) {
#pragma unroll
        for (int nt = 0; nt < 4; nt++)
#pragma unroll
            for (int v = 0; v < 4; v++) acc[mt][nt][v] = 0.0f;
#pragma unroll
        for (int v = 0; v < 4; v++) acc_e[mt][v] = 0.0f;
    }

    // prologue: chunks 0 and 1 in flight
    load_chunk(sb, wbase, tid);
    cp_commit();
    load_chunk(sb + STAGE_BYTES, wbase + KCHUNK, tid);
    cp_commit();

    for (int j = 0; j < nch; j++) {
        if (j + 2 < nch)
            load_chunk(sb + ((j + 2) % 3) * STAGE_BYTES,
                       wbase + (size_t)(j + 2) * KCHUNK, tid);
        cp_commit();                      // empty groups keep the count aligned
        cp_wait2();                       // chunk j resident
        __syncthreads();

        const float* As = smem + (j % 3) * STAGE_FLOATS;
        const int cb = (c0 + j) * 4;                  // base ck for this chunk

#pragma unroll
        for (int kst = 0; kst < 4; kst++) {
            const int k0 = kst * 8;
            // B fragments: coalesced 256B LDG.64 from packed buffer (L1-hot)
            const float2* bf = Bp2 + ((size_t)(cb + kst) * NFRAG + ng * 4) * 32 + lid;
            float2 b[4];
#pragma unroll
            for (int nt = 0; nt < 4; nt++) b[nt] = bf[nt * 32];
            float2 be = bf[(8 - ng * 4) * 32];        // shared fragment nn=8

            uint32_t a[2][4];
#pragma unroll
            for (int mt = 0; mt < 2; mt++) {
                const float* ap = As + (mg * 32 + mt * 16 + g) * RS + k0 + q;
                a[mt][0] = __float_as_uint(ap[0]);
                a[mt][1] = __float_as_uint(ap[8 * RS]);
                a[mt][2] = __float_as_uint(ap[4]);
                a[mt][3] = __float_as_uint(ap[8 * RS + 4]);
            }
#pragma unroll
            for (int nt = 0; nt < 4; nt++) {
                uint32_t bb[2] = { __float_as_uint(b[nt].x),
                                   __float_as_uint(b[nt].y) };
                mma_tf32(acc[0][nt], a[0], bb);
                mma_tf32(acc[1][nt], a[1], bb);
            }
            {
                uint32_t bb[2] = { __float_as_uint(be.x),
                                   __float_as_uint(be.y) };
                mma_tf32(acc_e[0], a[0], bb);
                mma_tf32(acc_e[1], a[1], bb);
            }
        }
        __syncthreads();
    }

    // ------------- epilogue: fold U with Y + extra cols, reduce -------------
    // row squared-norms for this thread's 4 fragment rows
    const int rbase = m0 + mg * 32 + g;
    float sqi[2][2];
    sqi[0][0] = g_sq[rbase];      sqi[0][1] = g_sq[rbase + 8];
    sqi[1][0] = g_sq[rbase + 16]; sqi[1][1] = g_sq[rbase + 24];

    float dot = 0.0f, extra = 0.0f;
#pragma unroll
    for (int mt = 0; mt < 2; mt++) {
        const int r0 = m0 + mg * 32 + mt * 16 + g;
#pragma unroll
        for (int nt = 0; nt < 4; nt++) {
            const int cc = ng * 32 + nt * 8 + 2 * q;
            float2 y0 = *(const float2*)(Y + (size_t)r0 * KF + cc);
            float2 y1 = *(const float2*)(Y + (size_t)(r0 + 8) * KF + cc);
            dot += acc[mt][nt][0] * y0.x + acc[mt][nt][1] * y0.y +
                   acc[mt][nt][2] * y1.x + acc[mt][nt][3] * y1.y;
        }
        // q==0 lanes hold cols 64 ((W·sq)_i, c0/c2) and 65 (rowsum r_i, c1/c3);
        // q>=1 lanes hold zero columns -> contribute exact 0.
        extra += acc_e[mt][0] + sqi[mt][0] * acc_e[mt][1] +
                 acc_e[mt][2] + sqi[mt][1] * acc_e[mt][3];
    }
    // both ng warp-groups computed the shared fragment -> halve it
    float total = 0.5f * extra - 2.0f * dot;
#pragma unroll
    for (int o = 16; o; o >>= 1)
        total += __shfl_xor_sync(0xffffffffu, total, o);

    __syncthreads();                   // stages dead; reuse smem for reduction
    if (lid == 0) smem[w] = total;
    __syncthreads();
    if (tid == 0) {
        float s = 0.0f;
#pragma unroll
        for (int i = 0; i < 8; i++) s += smem[i];
        atomicAdd(out, s * (1.0f / (2.0f * (float)N_DIM)));
    }
}

// ---------------------------------------------------------------- launch
extern "C" void kernel_launch(void* const* d_in, const int* in_sizes, int n_in,
                              void* d_out, int out_size) {
    const float* W = (const float*)d_in[0];
    const float* Y = (const float*)d_in[1];
    float* out = (float*)d_out;

    cudaFuncSetAttribute(spec_main, cudaFuncAttributeMaxDynamicSharedMemorySize,
                         SMEM_BYTES);

    spec_prep1<<<N_DIM / 256, 256>>>(Y, out);
    spec_prep2<<<(NCK * NFRAG * 32) / 256, 256>>>(Y);
    spec_main<<<64 * KSPLIT, 256, SMEM_BYTES>>>(W, Y, out);
}

// round 9
// speedup vs baseline: 1.1095x; 1.1095x over previous
#include <cuda_runtime.h>
#include <cstdint>

// ============================================================================
// SpectralNetLoss:
//   2n·loss = Σ_ij W_ij(sq_i + sq_j) − 2 Σ_ij W_ij (y_i·y_j)
// One tf32 mma.sync GEMM U = W × B̃,  B̃ = [Y | sq | 1 | 0…] (72 cols):
//   U[:,0..63] folded with Y -> dot term;  U[:,64]=(W·sq)_i, U[:,65]=r_i -> term1
// R9: (256,2) no-spill regs; 4-stage A-only cp.async pipeline (depth 3);
//     asymmetric frag split 4/5 with SMSP-balanced warp map; grid 576 (KSPLIT 9);
//     rna rounding on both operands (unbiased tf32); fused prep kernel.
// ============================================================================

#define N_DIM     8192
#define KF        64
#define M_TILE    128
#define KCHUNK    32
#define KSPLIT    9
#define RS        36                        // padded A row stride (floats)
#define NFRAG     9                         // 9 n8 fragments = 72 B̃ columns

#define A_FLOATS  (M_TILE * RS)             // 4608
#define STAGE_BYTES  (A_FLOATS * 4)         // 18432
#define N_STAGES  4
#define SMEM_BYTES   (N_STAGES * STAGE_BYTES)  // 73728

#define NCK       (N_DIM / 8)               // 1024 k-octets

// B̃ packed in mma-fragment order: float2[(ck*9 + nn)*32 + lane]
//   = ( B̃[ck*8+q][nn*8+g], B̃[ck*8+q+4][nn*8+g] ),  lane = g*4+q, rna-rounded
__device__ float g_Bp[(size_t)NCK * NFRAG * 64];
__device__ float g_sq[N_DIM];

// ---------------------------------------------------------------- helpers
__device__ __forceinline__ uint32_t smem_u32(const void* p) {
    uint32_t a;
    asm("{ .reg .u64 t; cvta.to.shared.u64 t, %1; cvt.u32.u64 %0, t; }"
        : "=r"(a) : "l"(p));
    return a;
}
__device__ __forceinline__ void cp_async16(uint32_t dst, const void* src) {
    asm volatile("cp.async.cg.shared.global [%0], [%1], 16;"
                 :: "r"(dst), "l"(src));
}
__device__ __forceinline__ void cp_commit() {
    asm volatile("cp.async.commit_group;" ::: "memory");
}
__device__ __forceinline__ void cp_wait3() {
    asm volatile("cp.async.wait_group 3;" ::: "memory");
}
__device__ __forceinline__ uint32_t tf32r(float f) {
    uint32_t r;
    asm("cvt.rna.tf32.f32 %0, %1;" : "=r"(r) : "f"(f));
    return r;
}
__device__ __forceinline__ void mma_tf32(float* c, const uint32_t* a,
                                         const uint32_t* b) {
    asm volatile(
        "mma.sync.aligned.m16n8k8.row.col.f32.tf32.tf32.f32 "
        "{%0,%1,%2,%3}, {%4,%5,%6,%7}, {%8,%9}, {%0,%1,%2,%3};"
        : "+f"(c[0]), "+f"(c[1]), "+f"(c[2]), "+f"(c[3])
        : "r"(a[0]), "r"(a[1]), "r"(a[2]), "r"(a[3]), "r"(b[0]), "r"(b[1]));
}

// ---------------------------------------------------------------- fused prep
// Block b handles k-rows [b*32, b*32+32): computes sq, packs+rounds B̃ frags.
__global__ void spec_prep(const float* __restrict__ Y, float* __restrict__ out) {
    __shared__ float sY[32 * 72];          // stride 72: conflict-free frag reads
    __shared__ float ssq[32];
    const int tid = threadIdx.x;
    const int b = blockIdx.x;
    const int k0 = b * 32;

    if (b == 0 && tid == 0) out[0] = 0.0f;

#pragma unroll
    for (int i = 0; i < 8; i++) {
        int idx = tid + i * 256;           // 0..2047, coalesced
        sY[(idx >> 6) * 72 + (idx & 63)] = Y[(size_t)k0 * KF + idx];
    }
    __syncthreads();

    {   // sq: 8 threads per row
        int r = tid >> 3, p = tid & 7;
        const float* row = sY + r * 72 + p * 8;
        float s = 0.0f;
#pragma unroll
        for (int c = 0; c < 8; c++) s += row[c] * row[c];
#pragma unroll
        for (int o = 4; o; o >>= 1) s += __shfl_xor_sync(0xffffffffu, s, o);
        if (p == 0) { ssq[r] = s; g_sq[k0 + r] = s; }
    }
    __syncthreads();

    float2* Bp2 = (float2*)g_Bp;
#pragma unroll
    for (int i = 0; i < 5; i++) {
        int u = tid + i * 256;             // 0..1151
        if (u >= 4 * NFRAG * 32) break;
        int lane = u & 31;
        int q = lane & 3, g = lane >> 2;
        int cn = u >> 5;                   // ckl*9 + nn
        int nn = cn % NFRAG, ckl = cn / NFRAG;
        int kl = ckl * 8 + q;
        float v0, v1;
        if (nn < 8) {
            int col = nn * 8 + g;
            v0 = sY[kl * 72 + col];
            v1 = sY[(kl + 4) * 72 + col];
        } else {
            v0 = (g == 0) ? ssq[kl]     : (g == 1 ? 1.0f : 0.0f);
            v1 = (g == 0) ? ssq[kl + 4] : (g == 1 ? 1.0f : 0.0f);
        }
        float2 o;
        o.x = __uint_as_float(tf32r(v0));
        o.y = __uint_as_float(tf32r(v1));
        Bp2[(size_t)b * (4 * NFRAG * 32) + u] = o;   // fully coalesced
    }
}

// ---------------------------------------------------------------- A loader
__device__ __forceinline__ void load_chunk(uint32_t sdst, const float* wp,
                                           int tid) {
#pragma unroll
    for (int u = 0; u < 4; u++) {
        int idx = tid + u * 256;                      // 128 rows x 8 float4
        int r = idx >> 3, sg = idx & 7;
        cp_async16(sdst + (uint32_t)(r * RS + sg * 4) * 4,
                   wp + (size_t)r * N_DIM + sg * 4);
    }
}

// ---------------------------------------------------------------- main
__global__ void __launch_bounds__(256, 2)
spec_main(const float* __restrict__ W, const float* __restrict__ Y,
          float* __restrict__ out) {
    extern __shared__ float smem[];
    const uint32_t sb = smem_u32(smem);

    const int tid = threadIdx.x;
    const int w   = tid >> 5;
    const int lid = tid & 31;
    const int q   = lid & 3;
    const int g   = lid >> 2;
    const int mg  = w & 3;             // 32-row group (one per SMSP)
    const int ng  = w >> 2;            // 0: frags 0..3 | 1: frags 4..8

    const int bx    = blockIdx.x;
    const int mtile = bx & 63;
    const int ks    = bx >> 6;                              // 0..8
    const int m0    = mtile * M_TILE;
    const int c0    = (ks < 4) ? ks * 29 : 116 + (ks - 4) * 28;
    const int nch   = (ks < 4) ? 29 : 28;

    const float* wbase = W + (size_t)m0 * N_DIM + (size_t)c0 * KCHUNK;
    const float2* Bp2  = (const float2*)g_Bp;

    float acc[2][5][4];
#pragma unroll
    for (int mt = 0; mt < 2; mt++)
#pragma unroll
        for (int nt = 0; nt < 5; nt++)
#pragma unroll
            for (int v = 0; v < 4; v++) acc[mt][nt][v] = 0.0f;

    // prologue: 3 chunks in flight
#pragma unroll
    for (int p = 0; p < 3; p++) {
        load_chunk(sb + p * STAGE_BYTES, wbase + (size_t)p * KCHUNK, tid);
        cp_commit();
    }

    for (int j = 0; j < nch; j++) {
        if (j + 3 < nch)
            load_chunk(sb + ((j + 3) & 3) * STAGE_BYTES,
                       wbase + (size_t)(j + 3) * KCHUNK, tid);
        cp_commit();                     // empty groups keep the count aligned
        cp_wait3();                      // chunk j resident
        __syncthreads();

        const float* As = smem + (j & 3) * A_FLOATS;
        const int cb = (c0 + j) * 4;

#pragma unroll
        for (int kst = 0; kst < 4; kst++) {
            const int k0 = kst * 8;
            // B fragments: coalesced LDG.64 from packed buffer (L2/L1-hot)
            const float2* bf =
                Bp2 + ((size_t)(cb + kst) * NFRAG + ng * 4) * 32 + lid;
            float2 b[4];
#pragma unroll
            for (int nt = 0; nt < 4; nt++) b[nt] = bf[nt * 32];

            uint32_t a[2][4];
#pragma unroll
            for (int mt = 0; mt < 2; mt++) {
                const float* ap = As + (mg * 32 + mt * 16 + g) * RS + k0 + q;
                a[mt][0] = tf32r(ap[0]);            // rna round -> unbiased
                a[mt][1] = tf32r(ap[8 * RS]);
                a[mt][2] = tf32r(ap[4]);
                a[mt][3] = tf32r(ap[8 * RS + 4]);
            }
#pragma unroll
            for (int nt = 0; nt < 4; nt++) {
                uint32_t bb[2] = { __float_as_uint(b[nt].x),
                                   __float_as_uint(b[nt].y) };
                mma_tf32(acc[0][nt], a[0], bb);
                mma_tf32(acc[1][nt], a[1], bb);
            }
            if (ng) {                   // 9th fragment (cols 64..71), ng1 only
                float2 be = bf[4 * 32];
                uint32_t bb[2] = { __float_as_uint(be.x),
                                   __float_as_uint(be.y) };
                mma_tf32(acc[0][4], a[0], bb);
                mma_tf32(acc[1][4], a[1], bb);
            }
        }
        __syncthreads();
    }

    // ------------- epilogue: fold U with Y + extra cols, reduce -------------
    const int rbase = m0 + mg * 32 + g;
    float sqi[2][2];
    sqi[0][0] = g_sq[rbase];      sqi[0][1] = g_sq[rbase + 8];
    sqi[1][0] = g_sq[rbase + 16]; sqi[1][1] = g_sq[rbase + 24];

    float dot = 0.0f, extra = 0.0f;
#pragma unroll
    for (int mt = 0; mt < 2; mt++) {
        const int r0 = m0 + mg * 32 + mt * 16 + g;
#pragma unroll
        for (int nt = 0; nt < 4; nt++) {
            const int cc = ng * 32 + nt * 8 + 2 * q;
            float2 y0 = *(const float2*)(Y + (size_t)r0 * KF + cc);
            float2 y1 = *(const float2*)(Y + (size_t)(r0 + 8) * KF + cc);
            dot += acc[mt][nt][0] * y0.x + acc[mt][nt][1] * y0.y +
                   acc[mt][nt][2] * y1.x + acc[mt][nt][3] * y1.y;
        }
        if (ng) {
            // q==0 lanes: col64=(W·sq)_i (v0/v2), col65=rowsum r_i (v1/v3);
            // q>=1 lanes hold zero columns -> exact 0 contribution.
            extra += acc[mt][4][0] + sqi[mt][0] * acc[mt][4][1] +
                     acc[mt][4][2] + sqi[mt][1] * acc[mt][4][3];
        }
    }
    float total = extra - 2.0f * dot;
#pragma unroll
    for (int o = 16; o; o >>= 1)
        total += __shfl_xor_sync(0xffffffffu, total, o);

    __syncthreads();                   // stages dead; reuse smem for reduction
    if (lid == 0) smem[w] = total;
    __syncthreads();
    if (tid == 0) {
        float s = 0.0f;
#pragma unroll
        for (int i = 0; i < 8; i++) s += smem[i];
        atomicAdd(out, s * (1.0f / (2.0f * (float)N_DIM)));
    }
}

// ---------------------------------------------------------------- launch
extern "C" void kernel_launch(void* const* d_in, const int* in_sizes, int n_in,
                              void* d_out, int out_size) {
    const float* W = (const float*)d_in[0];
    const float* Y = (const float*)d_in[1];
    float* out = (float*)d_out;

    cudaFuncSetAttribute(spec_main, cudaFuncAttributeMaxDynamicSharedMemorySize,
                         SMEM_BYTES);

    spec_prep<<<N_DIM / 32, 256>>>(Y, out);
    spec_main<<<64 * KSPLIT, 256, SMEM_BYTES>>>(W, Y, out);
}